// round 2
// baseline (speedup 1.0000x reference)
#include <cuda_runtime.h>
#include <cuda_bf16.h>
#include <cstdint>

// Problem constants (shapes fixed by the reference)
#define NMAX   50000
#define IND    128        // IN_DIM
#define HD     128        // HEADS * D
#define HEADS  8
#define DDIM   16

// Scratch for projected Q, K, V  ([N,128] each, fp32)
__device__ float g_Q[NMAX * HD];
__device__ float g_K[NMAX * HD];
__device__ float g_V[NMAX * HD];

// ---------------------------------------------------------------------------
// QKV projection GEMM:  out[N,128] = h[N,128] @ W[128,128] + b
// Block tile 128 rows x 128 cols, 256 threads, 8x8 micro-tile per thread.
// Smem layout is k-major (transposed h tile) so both operand reads are
// contiguous float4s along the fastest dim. Row stride 132 floats
// (132*4 = 528 bytes -> float4 alignment preserved, banks spread).
// grid.y selects which of Q/K/V this block computes.
// ---------------------------------------------------------------------------
#define GPAD 132
#define GEMM_SMEM_BYTES (2 * 128 * GPAD * 4)

__global__ __launch_bounds__(256)
void qkv_gemm(const float* __restrict__ h,
              const float* __restrict__ Wq, const float* __restrict__ bq,
              const float* __restrict__ Wk, const float* __restrict__ bk,
              const float* __restrict__ Wv, const float* __restrict__ bv,
              int n_nodes)
{
    extern __shared__ float smem[];
    float* hs = smem;                 // hs[k*GPAD + r]  (k-major h tile)
    float* ws = smem + 128 * GPAD;    // ws[k*GPAD + c]

    const float* W;
    const float* bias;
    float* out;
    if (blockIdx.y == 0)      { W = Wq; bias = bq; out = g_Q; }
    else if (blockIdx.y == 1) { W = Wk; bias = bk; out = g_K; }
    else                      { W = Wv; bias = bv; out = g_V; }

    const int row0 = blockIdx.x * 128;
    const int tid  = threadIdx.x;
    const int tx   = tid & 15;        // 0..15 -> col group
    const int ty   = tid >> 4;        // 0..15 -> row group

    // Cooperative loads: 16384 elements each, 64 per thread, coalesced gmem.
    #pragma unroll
    for (int i = 0; i < 64; i++) {
        int lin = tid + i * 256;
        int r = lin >> 7;             // 0..127
        int k = lin & 127;
        float v = 0.0f;
        int gr = row0 + r;
        if (gr < n_nodes) v = h[gr * IND + k];
        hs[k * GPAD + r] = v;
    }
    #pragma unroll
    for (int i = 0; i < 64; i++) {
        int lin = tid + i * 256;
        int k = lin >> 7;
        int c = lin & 127;
        ws[k * GPAD + c] = W[k * HD + c];
    }
    __syncthreads();

    float acc[8][8];
    #pragma unroll
    for (int j = 0; j < 8; j++) {
        float bv_ = bias[tx * 8 + j];
        #pragma unroll
        for (int i = 0; i < 8; i++) acc[i][j] = bv_;
    }

    const int ra = ty * 8;
    const int cb = tx * 8;
    #pragma unroll 4
    for (int k = 0; k < 128; k++) {
        float4 a0 = *(const float4*)&hs[k * GPAD + ra];
        float4 a1 = *(const float4*)&hs[k * GPAD + ra + 4];
        float4 b0 = *(const float4*)&ws[k * GPAD + cb];
        float4 b1 = *(const float4*)&ws[k * GPAD + cb + 4];
        float a[8] = {a0.x, a0.y, a0.z, a0.w, a1.x, a1.y, a1.z, a1.w};
        float b[8] = {b0.x, b0.y, b0.z, b0.w, b1.x, b1.y, b1.z, b1.w};
        #pragma unroll
        for (int i = 0; i < 8; i++)
            #pragma unroll
            for (int j = 0; j < 8; j++)
                acc[i][j] = fmaf(a[i], b[j], acc[i][j]);
    }

    // Store 8 rows x 8 cols as float4 pairs (coalesced across tx).
    #pragma unroll
    for (int i = 0; i < 8; i++) {
        int gr = row0 + ra + i;
        if (gr < n_nodes) {
            float4 s0 = make_float4(acc[i][0], acc[i][1], acc[i][2], acc[i][3]);
            float4 s1 = make_float4(acc[i][4], acc[i][5], acc[i][6], acc[i][7]);
            *(float4*)&out[gr * HD + cb]     = s0;
            *(float4*)&out[gr * HD + cb + 4] = s1;
        }
    }
}

// ---------------------------------------------------------------------------
// Edge phase: one warp per edge.
//   lane l handles floats [l*4, l*4+4) of the 128-float feature vector,
//   i.e. head h = l/4, dims (l%4)*4 .. +3.
//   score[h] = dot(K[src,h,:], Q[dst,h,:]) / sqrt(16)  (shfl-reduce over the
//   4 lanes of each head group), then red.global.add.v4.f32 of score*V[src]
//   into out[dst].
// ---------------------------------------------------------------------------
__global__ __launch_bounds__(256)
void edge_kernel(const int* __restrict__ src,
                 const int* __restrict__ dst,
                 float* __restrict__ out,
                 int n_edges)
{
    int gtid = blockIdx.x * blockDim.x + threadIdx.x;
    int e    = gtid >> 5;
    int lane = gtid & 31;
    if (e >= n_edges) return;

    int s = src[e];
    int d = dst[e];

    const float4* K4 = (const float4*)g_K;
    const float4* Q4 = (const float4*)g_Q;
    const float4* V4 = (const float4*)g_V;

    float4 kv = K4[s * 32 + lane];
    float4 qv = Q4[d * 32 + lane];
    float p = kv.x * qv.x + kv.y * qv.y + kv.z * qv.z + kv.w * qv.w;
    // reduce across the 4 lanes of this head group
    p += __shfl_xor_sync(0xffffffffu, p, 1);
    p += __shfl_xor_sync(0xffffffffu, p, 2);
    p *= 0.25f;   // 1/sqrt(D), D=16

    float4 v = V4[s * 32 + lane];
    float4 m = make_float4(v.x * p, v.y * p, v.z * p, v.w * p);

    float* dp = out + (size_t)d * HD + lane * 4;
    asm volatile("red.global.add.v4.f32 [%0], {%1, %2, %3, %4};"
                 :: "l"(dp), "f"(m.x), "f"(m.y), "f"(m.z), "f"(m.w)
                 : "memory");
}

// ---------------------------------------------------------------------------
// Launch
// ---------------------------------------------------------------------------
extern "C" void kernel_launch(void* const* d_in, const int* in_sizes, int n_in,
                              void* d_out, int out_size)
{
    const float* h   = (const float*)d_in[0];
    const int*   src = (const int*)  d_in[1];
    const int*   dst = (const int*)  d_in[2];
    const float* Wq  = (const float*)d_in[3];
    const float* bq  = (const float*)d_in[4];
    const float* Wk  = (const float*)d_in[5];
    const float* bk  = (const float*)d_in[6];
    const float* Wv  = (const float*)d_in[7];
    const float* bv  = (const float*)d_in[8];
    float* out = (float*)d_out;

    int n_nodes = in_sizes[0] / IND;   // 50000
    int n_edges = in_sizes[1];         // 800000

    // Unconditional (no static guard): idempotent host-side attribute set,
    // identical work on every call including the graph-capture call.
    cudaFuncSetAttribute(qkv_gemm,
                         cudaFuncAttributeMaxDynamicSharedMemorySize,
                         GEMM_SMEM_BYTES);

    // Output is poisoned; zero it (memset node in the graph).
    cudaMemsetAsync(d_out, 0, (size_t)out_size * sizeof(float));

    dim3 ggrid((n_nodes + 127) / 128, 3);
    qkv_gemm<<<ggrid, 256, GEMM_SMEM_BYTES>>>(h, Wq, bq, Wk, bk, Wv, bv, n_nodes);

    int warps_total = n_edges;                    // one warp per edge
    int threads = warps_total * 32;
    int blocks  = (threads + 255) / 256;
    edge_kernel<<<blocks, 256>>>(src, dst, out, n_edges);
}

// round 3
// speedup vs baseline: 1.0900x; 1.0900x over previous
#include <cuda_runtime.h>
#include <cuda_bf16.h>
#include <cstdint>

// Problem constants (shapes fixed by the reference)
#define NMAX   50000
#define IND    128        // IN_DIM
#define HD     128        // HEADS * D
#define HEADS  8
#define DDIM   16

// Scratch for projected Q, K, V  ([N,128] each, fp32)
__device__ float g_Q[NMAX * HD];
__device__ float g_K[NMAX * HD];
__device__ float g_V[NMAX * HD];

// ---------------------------------------------------------------------------
// QKV projection GEMM:  out[N,128] = h[N,128] @ W[128,128] + b
// (unchanged from R2 passing version — it sits at the fp32 FFMA issue floor)
// ---------------------------------------------------------------------------
#define GPAD 132
#define GEMM_SMEM_BYTES (2 * 128 * GPAD * 4)

__global__ __launch_bounds__(256)
void qkv_gemm(const float* __restrict__ h,
              const float* __restrict__ Wq, const float* __restrict__ bq,
              const float* __restrict__ Wk, const float* __restrict__ bk,
              const float* __restrict__ Wv, const float* __restrict__ bv,
              int n_nodes)
{
    extern __shared__ float smem[];
    float* hs = smem;                 // hs[k*GPAD + r]  (k-major h tile)
    float* ws = smem + 128 * GPAD;    // ws[k*GPAD + c]

    const float* W;
    const float* bias;
    float* out;
    if (blockIdx.y == 0)      { W = Wq; bias = bq; out = g_Q; }
    else if (blockIdx.y == 1) { W = Wk; bias = bk; out = g_K; }
    else                      { W = Wv; bias = bv; out = g_V; }

    const int row0 = blockIdx.x * 128;
    const int tid  = threadIdx.x;
    const int tx   = tid & 15;        // 0..15 -> col group
    const int ty   = tid >> 4;        // 0..15 -> row group

    #pragma unroll
    for (int i = 0; i < 64; i++) {
        int lin = tid + i * 256;
        int r = lin >> 7;             // 0..127
        int k = lin & 127;
        float v = 0.0f;
        int gr = row0 + r;
        if (gr < n_nodes) v = h[gr * IND + k];
        hs[k * GPAD + r] = v;
    }
    #pragma unroll
    for (int i = 0; i < 64; i++) {
        int lin = tid + i * 256;
        int k = lin >> 7;
        int c = lin & 127;
        ws[k * GPAD + c] = W[k * HD + c];
    }
    __syncthreads();

    float acc[8][8];
    #pragma unroll
    for (int j = 0; j < 8; j++) {
        float bv_ = bias[tx * 8 + j];
        #pragma unroll
        for (int i = 0; i < 8; i++) acc[i][j] = bv_;
    }

    const int ra = ty * 8;
    const int cb = tx * 8;
    #pragma unroll 4
    for (int k = 0; k < 128; k++) {
        float4 a0 = *(const float4*)&hs[k * GPAD + ra];
        float4 a1 = *(const float4*)&hs[k * GPAD + ra + 4];
        float4 b0 = *(const float4*)&ws[k * GPAD + cb];
        float4 b1 = *(const float4*)&ws[k * GPAD + cb + 4];
        float a[8] = {a0.x, a0.y, a0.z, a0.w, a1.x, a1.y, a1.z, a1.w};
        float b[8] = {b0.x, b0.y, b0.z, b0.w, b1.x, b1.y, b1.z, b1.w};
        #pragma unroll
        for (int i = 0; i < 8; i++)
            #pragma unroll
            for (int j = 0; j < 8; j++)
                acc[i][j] = fmaf(a[i], b[j], acc[i][j]);
    }

    #pragma unroll
    for (int i = 0; i < 8; i++) {
        int gr = row0 + ra + i;
        if (gr < n_nodes) {
            float4 s0 = make_float4(acc[i][0], acc[i][1], acc[i][2], acc[i][3]);
            float4 s1 = make_float4(acc[i][4], acc[i][5], acc[i][6], acc[i][7]);
            *(float4*)&out[gr * HD + cb]     = s0;
            *(float4*)&out[gr * HD + cb + 4] = s1;
        }
    }
}

// ---------------------------------------------------------------------------
// Edge phase: FOUR edges per warp for memory-level parallelism.
//   lane l owns floats [l*4, l*4+4) of the 128-float feature vector.
//   All 12 gather LDG.128s (K,Q,V for 4 edges) are issued before any
//   consumption -> MLP ~12 per warp (vs 3 in the one-edge-per-warp version),
//   hiding L2/DRAM latency. Scores reduced over 4-lane head groups via shfl,
//   messages scattered with red.global.add.v4.f32.
// ---------------------------------------------------------------------------
#define EPW 4   // edges per warp

__device__ __forceinline__ void red_add_v4(float* p, float4 m) {
    asm volatile("red.global.add.v4.f32 [%0], {%1, %2, %3, %4};"
                 :: "l"(p), "f"(m.x), "f"(m.y), "f"(m.z), "f"(m.w)
                 : "memory");
}

__global__ __launch_bounds__(256)
void edge_kernel(const int* __restrict__ src,
                 const int* __restrict__ dst,
                 float* __restrict__ out,
                 int n_edges)
{
    int gtid = blockIdx.x * blockDim.x + threadIdx.x;
    int warp = gtid >> 5;
    int lane = gtid & 31;
    int e0   = warp * EPW;
    if (e0 >= n_edges) return;

    const float4* K4 = (const float4*)g_K;
    const float4* Q4 = (const float4*)g_Q;
    const float4* V4 = (const float4*)g_V;

    if (e0 + EPW <= n_edges) {
        // Fast path: vector-load the 4 src and 4 dst indices (broadcast in L1).
        int4 sv = __ldg((const int4*)(src + e0));
        int4 dv = __ldg((const int4*)(dst + e0));

        // Issue ALL gathers up front (12 independent LDG.128 per thread).
        float4 k0 = __ldg(&K4[(size_t)sv.x * 32 + lane]);
        float4 k1 = __ldg(&K4[(size_t)sv.y * 32 + lane]);
        float4 k2 = __ldg(&K4[(size_t)sv.z * 32 + lane]);
        float4 k3 = __ldg(&K4[(size_t)sv.w * 32 + lane]);
        float4 q0 = __ldg(&Q4[(size_t)dv.x * 32 + lane]);
        float4 q1 = __ldg(&Q4[(size_t)dv.y * 32 + lane]);
        float4 q2 = __ldg(&Q4[(size_t)dv.z * 32 + lane]);
        float4 q3 = __ldg(&Q4[(size_t)dv.w * 32 + lane]);
        float4 v0 = __ldg(&V4[(size_t)sv.x * 32 + lane]);
        float4 v1 = __ldg(&V4[(size_t)sv.y * 32 + lane]);
        float4 v2 = __ldg(&V4[(size_t)sv.z * 32 + lane]);
        float4 v3 = __ldg(&V4[(size_t)sv.w * 32 + lane]);

        float p0 = k0.x*q0.x + k0.y*q0.y + k0.z*q0.z + k0.w*q0.w;
        float p1 = k1.x*q1.x + k1.y*q1.y + k1.z*q1.z + k1.w*q1.w;
        float p2 = k2.x*q2.x + k2.y*q2.y + k2.z*q2.z + k2.w*q2.w;
        float p3 = k3.x*q3.x + k3.y*q3.y + k3.z*q3.z + k3.w*q3.w;

        p0 += __shfl_xor_sync(0xffffffffu, p0, 1);
        p1 += __shfl_xor_sync(0xffffffffu, p1, 1);
        p2 += __shfl_xor_sync(0xffffffffu, p2, 1);
        p3 += __shfl_xor_sync(0xffffffffu, p3, 1);
        p0 += __shfl_xor_sync(0xffffffffu, p0, 2);
        p1 += __shfl_xor_sync(0xffffffffu, p1, 2);
        p2 += __shfl_xor_sync(0xffffffffu, p2, 2);
        p3 += __shfl_xor_sync(0xffffffffu, p3, 2);
        p0 *= 0.25f; p1 *= 0.25f; p2 *= 0.25f; p3 *= 0.25f;  // 1/sqrt(16)

        int lo = lane * 4;
        red_add_v4(out + (size_t)dv.x * HD + lo,
                   make_float4(v0.x*p0, v0.y*p0, v0.z*p0, v0.w*p0));
        red_add_v4(out + (size_t)dv.y * HD + lo,
                   make_float4(v1.x*p1, v1.y*p1, v1.z*p1, v1.w*p1));
        red_add_v4(out + (size_t)dv.z * HD + lo,
                   make_float4(v2.x*p2, v2.y*p2, v2.z*p2, v2.w*p2));
        red_add_v4(out + (size_t)dv.w * HD + lo,
                   make_float4(v3.x*p3, v3.y*p3, v3.z*p3, v3.w*p3));
    } else {
        // Tail: per-edge path.
        for (int i = 0; i < EPW; i++) {
            int e = e0 + i;
            if (e >= n_edges) break;
            int s = __ldg(src + e);
            int d = __ldg(dst + e);
            float4 kv = __ldg(&K4[(size_t)s * 32 + lane]);
            float4 qv = __ldg(&Q4[(size_t)s == (size_t)s ? (size_t)d * 32 + lane : 0]);
            float p = kv.x*qv.x + kv.y*qv.y + kv.z*qv.z + kv.w*qv.w;
            p += __shfl_xor_sync(0xffffffffu, p, 1);
            p += __shfl_xor_sync(0xffffffffu, p, 2);
            p *= 0.25f;
            float4 v = __ldg(&V4[(size_t)s * 32 + lane]);
            red_add_v4(out + (size_t)d * HD + lane * 4,
                       make_float4(v.x*p, v.y*p, v.z*p, v.w*p));
        }
    }
}

// ---------------------------------------------------------------------------
// Launch
// ---------------------------------------------------------------------------
extern "C" void kernel_launch(void* const* d_in, const int* in_sizes, int n_in,
                              void* d_out, int out_size)
{
    const float* h   = (const float*)d_in[0];
    const int*   src = (const int*)  d_in[1];
    const int*   dst = (const int*)  d_in[2];
    const float* Wq  = (const float*)d_in[3];
    const float* bq  = (const float*)d_in[4];
    const float* Wk  = (const float*)d_in[5];
    const float* bk  = (const float*)d_in[6];
    const float* Wv  = (const float*)d_in[7];
    const float* bv  = (const float*)d_in[8];
    float* out = (float*)d_out;

    int n_nodes = in_sizes[0] / IND;   // 50000
    int n_edges = in_sizes[1];         // 800000

    // Unconditional (no static guard): idempotent host-side attribute set.
    cudaFuncSetAttribute(qkv_gemm,
                         cudaFuncAttributeMaxDynamicSharedMemorySize,
                         GEMM_SMEM_BYTES);

    // Output is poisoned; zero it (memset node in the graph).
    cudaMemsetAsync(d_out, 0, (size_t)out_size * sizeof(float));

    dim3 ggrid((n_nodes + 127) / 128, 3);
    qkv_gemm<<<ggrid, 256, GEMM_SMEM_BYTES>>>(h, Wq, bq, Wk, bk, Wv, bv, n_nodes);

    int n_warps = (n_edges + EPW - 1) / EPW;
    long long threads = (long long)n_warps * 32;
    int blocks = (int)((threads + 255) / 256);
    edge_kernel<<<blocks, 256>>>(src, dst, out, n_edges);
}

// round 4
// speedup vs baseline: 1.5715x; 1.4418x over previous
#include <cuda_runtime.h>
#include <cuda_bf16.h>
#include <cstdint>

// Problem constants (shapes fixed by the reference)
#define NMAX   50000
#define IND    128        // IN_DIM
#define HD     128        // HEADS * D
#define HEADS  8
#define DDIM   16

// Scratch for projected Q, K, V  ([N,128] each, fp32)
__device__ float g_Q[NMAX * HD];
__device__ float g_K[NMAX * HD];
__device__ float g_V[NMAX * HD];

// ---------------------------------------------------------------------------
// QKV projection GEMM (tf32 tensor-core version)
//   out[N,128] = h[N,128] @ W[128,128] + b
// CTA tile: 128 rows x 128 cols, 256 threads = 8 warps in a 4(m) x 2(n) grid.
// Each warp computes 32x64 with mma.sync.m16n8k8 tf32 fragments (2 m-tiles x
// 8 n-tiles x 16 k-steps). Inputs are tf32-converted once when staged into
// shared memory.
//   A smem: row-major [r][k], stride 132 -> A-frag banks = 4g+t (conflict-free)
//   W smem: [k][n],            stride 136 -> B-frag banks = 8t+g (conflict-free)
// grid.y selects which of Q/K/V this block computes.
// ---------------------------------------------------------------------------
#define APAD 132
#define BPAD 136
#define GEMM_SMEM_BYTES ((128 * APAD + 128 * BPAD) * 4)

__device__ __forceinline__ uint32_t f32_to_tf32(float v) {
    uint32_t r;
    asm("cvt.rna.tf32.f32 %0, %1;" : "=r"(r) : "f"(v));
    return r;
}

__device__ __forceinline__ void mma_tf32(float c[4],
                                         uint32_t a0, uint32_t a1,
                                         uint32_t a2, uint32_t a3,
                                         uint32_t b0, uint32_t b1) {
    asm volatile(
        "mma.sync.aligned.m16n8k8.row.col.f32.tf32.tf32.f32 "
        "{%0,%1,%2,%3}, {%4,%5,%6,%7}, {%8,%9}, {%0,%1,%2,%3};"
        : "+f"(c[0]), "+f"(c[1]), "+f"(c[2]), "+f"(c[3])
        : "r"(a0), "r"(a1), "r"(a2), "r"(a3), "r"(b0), "r"(b1));
}

__global__ __launch_bounds__(256)
void qkv_gemm(const float* __restrict__ h,
              const float* __restrict__ Wq, const float* __restrict__ bq,
              const float* __restrict__ Wk, const float* __restrict__ bk,
              const float* __restrict__ Wv, const float* __restrict__ bv,
              int n_nodes)
{
    extern __shared__ uint32_t smem[];
    uint32_t* as = smem;                 // as[r*APAD + k]  (tf32 bits)
    uint32_t* ws = smem + 128 * APAD;    // ws[k*BPAD + n]  (tf32 bits)

    const float* W;
    const float* bias;
    float* out;
    if (blockIdx.y == 0)      { W = Wq; bias = bq; out = g_Q; }
    else if (blockIdx.y == 1) { W = Wk; bias = bk; out = g_K; }
    else                      { W = Wv; bias = bv; out = g_V; }

    const int row0 = blockIdx.x * 128;
    const int tid  = threadIdx.x;

    // Stage A (h tile): 16384 elems, coalesced; convert to tf32 bits.
    #pragma unroll
    for (int i = 0; i < 64; i++) {
        int lin = tid + i * 256;
        int r = lin >> 7;
        int k = lin & 127;
        float v = 0.0f;
        int gr = row0 + r;
        if (gr < n_nodes) v = h[gr * IND + k];
        as[r * APAD + k] = f32_to_tf32(v);
    }
    // Stage W tile: already [k][n] row-major in gmem.
    #pragma unroll
    for (int i = 0; i < 64; i++) {
        int lin = tid + i * 256;
        int k = lin >> 7;
        int n = lin & 127;
        ws[k * BPAD + n] = f32_to_tf32(W[k * HD + n]);
    }
    __syncthreads();

    const int warp   = tid >> 5;
    const int lane   = tid & 31;
    const int g      = lane >> 2;       // 0..7
    const int t      = lane & 3;        // 0..3
    const int warp_m = warp & 3;        // 0..3  -> rows warp_m*32
    const int warp_n = warp >> 2;       // 0..1  -> cols warp_n*64

    // Accumulators: 2 m-tiles x 8 n-tiles x 4 regs, init with bias.
    float c[2][8][4];
    #pragma unroll
    for (int ni = 0; ni < 8; ni++) {
        int col = warp_n * 64 + ni * 8 + 2 * t;
        float b0 = bias[col];
        float b1 = bias[col + 1];
        #pragma unroll
        for (int mi = 0; mi < 2; mi++) {
            c[mi][ni][0] = b0; c[mi][ni][1] = b1;
            c[mi][ni][2] = b0; c[mi][ni][3] = b1;
        }
    }

    const uint32_t* a_base = as + (warp_m * 32 + g) * APAD;  // + t + k0 (+8 rows)
    const uint32_t* b_base = ws + warp_n * 64 + g;           // + (k0+t)*BPAD + ni*8

    #pragma unroll
    for (int kk = 0; kk < 16; kk++) {
        const int k0 = kk * 8;

        uint32_t a[2][4];
        #pragma unroll
        for (int mi = 0; mi < 2; mi++) {
            const uint32_t* ap = a_base + mi * 16 * APAD + k0 + t;
            a[mi][0] = ap[0];
            a[mi][1] = ap[8 * APAD];
            a[mi][2] = ap[4];
            a[mi][3] = ap[8 * APAD + 4];
        }

        uint32_t b[8][2];
        const uint32_t* bp = b_base + (k0 + t) * BPAD;
        #pragma unroll
        for (int ni = 0; ni < 8; ni++) {
            b[ni][0] = bp[ni * 8];
            b[ni][1] = bp[ni * 8 + 4 * BPAD];
        }

        #pragma unroll
        for (int mi = 0; mi < 2; mi++)
            #pragma unroll
            for (int ni = 0; ni < 8; ni++)
                mma_tf32(c[mi][ni], a[mi][0], a[mi][1], a[mi][2], a[mi][3],
                         b[ni][0], b[ni][1]);
    }

    // Epilogue: c0/c1 -> row m0+g, cols n0+2t..+1 ; c2/c3 -> row m0+g+8.
    #pragma unroll
    for (int mi = 0; mi < 2; mi++) {
        int r_lo = row0 + warp_m * 32 + mi * 16 + g;
        #pragma unroll
        for (int ni = 0; ni < 8; ni++) {
            int col = warp_n * 64 + ni * 8 + 2 * t;
            if (r_lo < n_nodes)
                *(float2*)&out[(size_t)r_lo * HD + col] =
                    make_float2(c[mi][ni][0], c[mi][ni][1]);
            if (r_lo + 8 < n_nodes)
                *(float2*)&out[(size_t)(r_lo + 8) * HD + col] =
                    make_float2(c[mi][ni][2], c[mi][ni][3]);
        }
    }
}

// ---------------------------------------------------------------------------
// Edge phase: FOUR edges per warp (unchanged from R3 passing version).
// ---------------------------------------------------------------------------
#define EPW 4   // edges per warp

__device__ __forceinline__ void red_add_v4(float* p, float4 m) {
    asm volatile("red.global.add.v4.f32 [%0], {%1, %2, %3, %4};"
                 :: "l"(p), "f"(m.x), "f"(m.y), "f"(m.z), "f"(m.w)
                 : "memory");
}

__global__ __launch_bounds__(256)
void edge_kernel(const int* __restrict__ src,
                 const int* __restrict__ dst,
                 float* __restrict__ out,
                 int n_edges)
{
    int gtid = blockIdx.x * blockDim.x + threadIdx.x;
    int warp = gtid >> 5;
    int lane = gtid & 31;
    int e0   = warp * EPW;
    if (e0 >= n_edges) return;

    const float4* K4 = (const float4*)g_K;
    const float4* Q4 = (const float4*)g_Q;
    const float4* V4 = (const float4*)g_V;

    if (e0 + EPW <= n_edges) {
        int4 sv = __ldg((const int4*)(src + e0));
        int4 dv = __ldg((const int4*)(dst + e0));

        float4 k0 = __ldg(&K4[(size_t)sv.x * 32 + lane]);
        float4 k1 = __ldg(&K4[(size_t)sv.y * 32 + lane]);
        float4 k2 = __ldg(&K4[(size_t)sv.z * 32 + lane]);
        float4 k3 = __ldg(&K4[(size_t)sv.w * 32 + lane]);
        float4 q0 = __ldg(&Q4[(size_t)dv.x * 32 + lane]);
        float4 q1 = __ldg(&Q4[(size_t)dv.y * 32 + lane]);
        float4 q2 = __ldg(&Q4[(size_t)dv.z * 32 + lane]);
        float4 q3 = __ldg(&Q4[(size_t)dv.w * 32 + lane]);
        float4 v0 = __ldg(&V4[(size_t)sv.x * 32 + lane]);
        float4 v1 = __ldg(&V4[(size_t)sv.y * 32 + lane]);
        float4 v2 = __ldg(&V4[(size_t)sv.z * 32 + lane]);
        float4 v3 = __ldg(&V4[(size_t)sv.w * 32 + lane]);

        float p0 = k0.x*q0.x + k0.y*q0.y + k0.z*q0.z + k0.w*q0.w;
        float p1 = k1.x*q1.x + k1.y*q1.y + k1.z*q1.z + k1.w*q1.w;
        float p2 = k2.x*q2.x + k2.y*q2.y + k2.z*q2.z + k2.w*q2.w;
        float p3 = k3.x*q3.x + k3.y*q3.y + k3.z*q3.z + k3.w*q3.w;

        p0 += __shfl_xor_sync(0xffffffffu, p0, 1);
        p1 += __shfl_xor_sync(0xffffffffu, p1, 1);
        p2 += __shfl_xor_sync(0xffffffffu, p2, 1);
        p3 += __shfl_xor_sync(0xffffffffu, p3, 1);
        p0 += __shfl_xor_sync(0xffffffffu, p0, 2);
        p1 += __shfl_xor_sync(0xffffffffu, p1, 2);
        p2 += __shfl_xor_sync(0xffffffffu, p2, 2);
        p3 += __shfl_xor_sync(0xffffffffu, p3, 2);
        p0 *= 0.25f; p1 *= 0.25f; p2 *= 0.25f; p3 *= 0.25f;  // 1/sqrt(16)

        int lo = lane * 4;
        red_add_v4(out + (size_t)dv.x * HD + lo,
                   make_float4(v0.x*p0, v0.y*p0, v0.z*p0, v0.w*p0));
        red_add_v4(out + (size_t)dv.y * HD + lo,
                   make_float4(v1.x*p1, v1.y*p1, v1.z*p1, v1.w*p1));
        red_add_v4(out + (size_t)dv.z * HD + lo,
                   make_float4(v2.x*p2, v2.y*p2, v2.z*p2, v2.w*p2));
        red_add_v4(out + (size_t)dv.w * HD + lo,
                   make_float4(v3.x*p3, v3.y*p3, v3.z*p3, v3.w*p3));
    } else {
        for (int i = 0; i < EPW; i++) {
            int e = e0 + i;
            if (e >= n_edges) break;
            int s = __ldg(src + e);
            int d = __ldg(dst + e);
            float4 kv = __ldg(&K4[(size_t)s * 32 + lane]);
            float4 qv = __ldg(&Q4[(size_t)d * 32 + lane]);
            float p = kv.x*qv.x + kv.y*qv.y + kv.z*qv.z + kv.w*qv.w;
            p += __shfl_xor_sync(0xffffffffu, p, 1);
            p += __shfl_xor_sync(0xffffffffu, p, 2);
            p *= 0.25f;
            float4 v = __ldg(&V4[(size_t)s * 32 + lane]);
            red_add_v4(out + (size_t)d * HD + lane * 4,
                       make_float4(v.x*p, v.y*p, v.z*p, v.w*p));
        }
    }
}

// ---------------------------------------------------------------------------
// Launch
// ---------------------------------------------------------------------------
extern "C" void kernel_launch(void* const* d_in, const int* in_sizes, int n_in,
                              void* d_out, int out_size)
{
    const float* h   = (const float*)d_in[0];
    const int*   src = (const int*)  d_in[1];
    const int*   dst = (const int*)  d_in[2];
    const float* Wq  = (const float*)d_in[3];
    const float* bq  = (const float*)d_in[4];
    const float* Wk  = (const float*)d_in[5];
    const float* bk  = (const float*)d_in[6];
    const float* Wv  = (const float*)d_in[7];
    const float* bv  = (const float*)d_in[8];
    float* out = (float*)d_out;

    int n_nodes = in_sizes[0] / IND;   // 50000
    int n_edges = in_sizes[1];         // 800000

    // Unconditional (no static guard): idempotent host-side attribute set.
    cudaFuncSetAttribute(qkv_gemm,
                         cudaFuncAttributeMaxDynamicSharedMemorySize,
                         GEMM_SMEM_BYTES);

    // Output is poisoned; zero it (memset node in the graph).
    cudaMemsetAsync(d_out, 0, (size_t)out_size * sizeof(float));

    dim3 ggrid((n_nodes + 127) / 128, 3);
    qkv_gemm<<<ggrid, 256, GEMM_SMEM_BYTES>>>(h, Wq, bq, Wk, bk, Wv, bv, n_nodes);

    int n_warps = (n_edges + EPW - 1) / EPW;
    long long threads = (long long)n_warps * 32;
    int blocks = (int)((threads + 255) / 256);
    edge_kernel<<<blocks, 256>>>(src, dst, out, n_edges);
}

// round 5
// speedup vs baseline: 1.8042x; 1.1481x over previous
#include <cuda_runtime.h>
#include <cuda_bf16.h>
#include <cstdint>

// Problem constants (shapes fixed by the reference)
#define NMAX   50000
#define EMAX   800000
#define IND    128        // IN_DIM
#define HD     128        // HEADS * D
#define HEADS  8
#define DDIM   16

// Scratch for projected Q, K, V  ([N,128] each, fp32)
__device__ float g_Q[NMAX * HD];
__device__ float g_K[NMAX * HD];
__device__ float g_V[NMAX * HD];

// CSR-by-dst build scratch
__device__ int g_deg[NMAX];
__device__ int g_scantmp[NMAX];
__device__ int g_bsums[64];
__device__ int g_boffs[64];
__device__ int g_rowstart[NMAX + 1];
__device__ int g_cursor[NMAX];
__device__ int g_src_sorted[EMAX];

// ---------------------------------------------------------------------------
// QKV projection GEMM (tf32 tensor-core, unchanged from R4 passing version)
// ---------------------------------------------------------------------------
#define APAD 132
#define BPAD 136
#define GEMM_SMEM_BYTES ((128 * APAD + 128 * BPAD) * 4)

__device__ __forceinline__ uint32_t f32_to_tf32(float v) {
    uint32_t r;
    asm("cvt.rna.tf32.f32 %0, %1;" : "=r"(r) : "f"(v));
    return r;
}

__device__ __forceinline__ void mma_tf32(float c[4],
                                         uint32_t a0, uint32_t a1,
                                         uint32_t a2, uint32_t a3,
                                         uint32_t b0, uint32_t b1) {
    asm volatile(
        "mma.sync.aligned.m16n8k8.row.col.f32.tf32.tf32.f32 "
        "{%0,%1,%2,%3}, {%4,%5,%6,%7}, {%8,%9}, {%0,%1,%2,%3};"
        : "+f"(c[0]), "+f"(c[1]), "+f"(c[2]), "+f"(c[3])
        : "r"(a0), "r"(a1), "r"(a2), "r"(a3), "r"(b0), "r"(b1));
}

__global__ __launch_bounds__(256)
void qkv_gemm(const float* __restrict__ h,
              const float* __restrict__ Wq, const float* __restrict__ bq,
              const float* __restrict__ Wk, const float* __restrict__ bk,
              const float* __restrict__ Wv, const float* __restrict__ bv,
              int n_nodes)
{
    extern __shared__ uint32_t smem[];
    uint32_t* as = smem;                 // as[r*APAD + k]  (tf32 bits)
    uint32_t* ws = smem + 128 * APAD;    // ws[k*BPAD + n]  (tf32 bits)

    const float* W;
    const float* bias;
    float* out;
    if (blockIdx.y == 0)      { W = Wq; bias = bq; out = g_Q; }
    else if (blockIdx.y == 1) { W = Wk; bias = bk; out = g_K; }
    else                      { W = Wv; bias = bv; out = g_V; }

    const int row0 = blockIdx.x * 128;
    const int tid  = threadIdx.x;

    #pragma unroll
    for (int i = 0; i < 64; i++) {
        int lin = tid + i * 256;
        int r = lin >> 7;
        int k = lin & 127;
        float v = 0.0f;
        int gr = row0 + r;
        if (gr < n_nodes) v = h[gr * IND + k];
        as[r * APAD + k] = f32_to_tf32(v);
    }
    #pragma unroll
    for (int i = 0; i < 64; i++) {
        int lin = tid + i * 256;
        int k = lin >> 7;
        int n = lin & 127;
        ws[k * BPAD + n] = f32_to_tf32(W[k * HD + n]);
    }
    __syncthreads();

    const int warp   = tid >> 5;
    const int lane   = tid & 31;
    const int g      = lane >> 2;       // 0..7
    const int t      = lane & 3;        // 0..3
    const int warp_m = warp & 3;        // 0..3
    const int warp_n = warp >> 2;       // 0..1

    float c[2][8][4];
    #pragma unroll
    for (int ni = 0; ni < 8; ni++) {
        int col = warp_n * 64 + ni * 8 + 2 * t;
        float b0 = bias[col];
        float b1 = bias[col + 1];
        #pragma unroll
        for (int mi = 0; mi < 2; mi++) {
            c[mi][ni][0] = b0; c[mi][ni][1] = b1;
            c[mi][ni][2] = b0; c[mi][ni][3] = b1;
        }
    }

    const uint32_t* a_base = as + (warp_m * 32 + g) * APAD;
    const uint32_t* b_base = ws + warp_n * 64 + g;

    #pragma unroll
    for (int kk = 0; kk < 16; kk++) {
        const int k0 = kk * 8;

        uint32_t a[2][4];
        #pragma unroll
        for (int mi = 0; mi < 2; mi++) {
            const uint32_t* ap = a_base + mi * 16 * APAD + k0 + t;
            a[mi][0] = ap[0];
            a[mi][1] = ap[8 * APAD];
            a[mi][2] = ap[4];
            a[mi][3] = ap[8 * APAD + 4];
        }

        uint32_t b[8][2];
        const uint32_t* bp = b_base + (k0 + t) * BPAD;
        #pragma unroll
        for (int ni = 0; ni < 8; ni++) {
            b[ni][0] = bp[ni * 8];
            b[ni][1] = bp[ni * 8 + 4 * BPAD];
        }

        #pragma unroll
        for (int mi = 0; mi < 2; mi++)
            #pragma unroll
            for (int ni = 0; ni < 8; ni++)
                mma_tf32(c[mi][ni], a[mi][0], a[mi][1], a[mi][2], a[mi][3],
                         b[ni][0], b[ni][1]);
    }

    #pragma unroll
    for (int mi = 0; mi < 2; mi++) {
        int r_lo = row0 + warp_m * 32 + mi * 16 + g;
        #pragma unroll
        for (int ni = 0; ni < 8; ni++) {
            int col = warp_n * 64 + ni * 8 + 2 * t;
            if (r_lo < n_nodes)
                *(float2*)&out[(size_t)r_lo * HD + col] =
                    make_float2(c[mi][ni][0], c[mi][ni][1]);
            if (r_lo + 8 < n_nodes)
                *(float2*)&out[(size_t)(r_lo + 8) * HD + col] =
                    make_float2(c[mi][ni][2], c[mi][ni][3]);
        }
    }
}

// ---------------------------------------------------------------------------
// CSR-by-dst build: histogram -> 3-step exclusive scan -> stable-ish scatter.
// ---------------------------------------------------------------------------
__global__ __launch_bounds__(256)
void hist_kernel(const int* __restrict__ dst, int n_edges)
{
    int e = blockIdx.x * blockDim.x + threadIdx.x;
    if (e < n_edges) atomicAdd(&g_deg[dst[e]], 1);
}

// Block-exclusive scan of 1024 elements per block; writes block sums.
__global__ __launch_bounds__(1024)
void scan1_kernel(int n)
{
    __shared__ int wsum[32];
    int tid  = threadIdx.x;
    int lane = tid & 31, wid = tid >> 5;
    int i = blockIdx.x * 1024 + tid;
    int v = (i < n) ? g_deg[i] : 0;
    int x = v;
    #pragma unroll
    for (int o = 1; o < 32; o <<= 1) {
        int y = __shfl_up_sync(0xffffffffu, x, o);
        if (lane >= o) x += y;
    }
    if (lane == 31) wsum[wid] = x;
    __syncthreads();
    if (wid == 0) {
        int w = wsum[lane];
        #pragma unroll
        for (int o = 1; o < 32; o <<= 1) {
            int y = __shfl_up_sync(0xffffffffu, w, o);
            if (lane >= o) w += y;
        }
        wsum[lane] = w;  // inclusive warp totals
    }
    __syncthreads();
    int woff = (wid > 0) ? wsum[wid - 1] : 0;
    if (i < n) g_scantmp[i] = woff + x - v;          // exclusive within block
    if (tid == 1023) g_bsums[blockIdx.x] = woff + x; // block total
}

// Exclusive scan of the (<=64) block sums. Single block.
__global__ __launch_bounds__(64)
void scan2_kernel(int nb)
{
    int tid = threadIdx.x;
    int v = (tid < nb) ? g_bsums[tid] : 0;
    int lane = tid & 31, wid = tid >> 5;
    __shared__ int wtot[2];
    int x = v;
    #pragma unroll
    for (int o = 1; o < 32; o <<= 1) {
        int y = __shfl_up_sync(0xffffffffu, x, o);
        if (lane >= o) x += y;
    }
    if (lane == 31) wtot[wid] = x;
    __syncthreads();
    int woff = (wid == 1) ? wtot[0] : 0;
    if (tid < nb) g_boffs[tid] = woff + x - v;
}

// Combine, emit rowstart + cursor copy; rowstart[n] = n_edges.
__global__ __launch_bounds__(1024)
void scan3_kernel(int n, int n_edges)
{
    int i = blockIdx.x * 1024 + threadIdx.x;
    if (i < n) {
        int r = g_scantmp[i] + g_boffs[i >> 10];
        g_rowstart[i] = r;
        g_cursor[i]   = r;
    }
    if (i == n) g_rowstart[n] = n_edges;
}

__global__ __launch_bounds__(256)
void scatter_kernel(const int* __restrict__ src, const int* __restrict__ dst,
                    int n_edges)
{
    int e = blockIdx.x * blockDim.x + threadIdx.x;
    if (e < n_edges) {
        int pos = atomicAdd(&g_cursor[dst[e]], 1);
        g_src_sorted[pos] = src[e];
    }
}

// ---------------------------------------------------------------------------
// Aggregation: one warp per destination node. No atomics.
//   lane l owns floats [l*4, l*4+4) (head l/4, dims (l%4)*4..+3).
//   Q[d] loaded once; in-edges consumed 4 at a time (8 independent LDG.128
//   per lane per chunk for MLP); one plain float4 store per lane at the end.
// ---------------------------------------------------------------------------
__global__ __launch_bounds__(256)
void aggregate_kernel(float* __restrict__ out, int n_nodes)
{
    int gtid = blockIdx.x * blockDim.x + threadIdx.x;
    int d    = gtid >> 5;
    int lane = gtid & 31;
    if (d >= n_nodes) return;

    const float4* K4 = (const float4*)g_K;
    const float4* Q4 = (const float4*)g_Q;
    const float4* V4 = (const float4*)g_V;

    float4 q = __ldg(&Q4[(size_t)d * 32 + lane]);
    int beg = g_rowstart[d];
    int end = g_rowstart[d + 1];

    float4 acc = make_float4(0.f, 0.f, 0.f, 0.f);

    int e = beg;
    for (; e + 4 <= end; e += 4) {
        int s0 = __ldg(g_src_sorted + e);
        int s1 = __ldg(g_src_sorted + e + 1);
        int s2 = __ldg(g_src_sorted + e + 2);
        int s3 = __ldg(g_src_sorted + e + 3);

        float4 k0 = __ldg(&K4[(size_t)s0 * 32 + lane]);
        float4 k1 = __ldg(&K4[(size_t)s1 * 32 + lane]);
        float4 k2 = __ldg(&K4[(size_t)s2 * 32 + lane]);
        float4 k3 = __ldg(&K4[(size_t)s3 * 32 + lane]);
        float4 v0 = __ldg(&V4[(size_t)s0 * 32 + lane]);
        float4 v1 = __ldg(&V4[(size_t)s1 * 32 + lane]);
        float4 v2 = __ldg(&V4[(size_t)s2 * 32 + lane]);
        float4 v3 = __ldg(&V4[(size_t)s3 * 32 + lane]);

        float p0 = k0.x*q.x + k0.y*q.y + k0.z*q.z + k0.w*q.w;
        float p1 = k1.x*q.x + k1.y*q.y + k1.z*q.z + k1.w*q.w;
        float p2 = k2.x*q.x + k2.y*q.y + k2.z*q.z + k2.w*q.w;
        float p3 = k3.x*q.x + k3.y*q.y + k3.z*q.z + k3.w*q.w;

        p0 += __shfl_xor_sync(0xffffffffu, p0, 1);
        p1 += __shfl_xor_sync(0xffffffffu, p1, 1);
        p2 += __shfl_xor_sync(0xffffffffu, p2, 1);
        p3 += __shfl_xor_sync(0xffffffffu, p3, 1);
        p0 += __shfl_xor_sync(0xffffffffu, p0, 2);
        p1 += __shfl_xor_sync(0xffffffffu, p1, 2);
        p2 += __shfl_xor_sync(0xffffffffu, p2, 2);
        p3 += __shfl_xor_sync(0xffffffffu, p3, 2);
        p0 *= 0.25f; p1 *= 0.25f; p2 *= 0.25f; p3 *= 0.25f;  // 1/sqrt(16)

        acc.x += p0*v0.x + p1*v1.x + p2*v2.x + p3*v3.x;
        acc.y += p0*v0.y + p1*v1.y + p2*v2.y + p3*v3.y;
        acc.z += p0*v0.z + p1*v1.z + p2*v2.z + p3*v3.z;
        acc.w += p0*v0.w + p1*v1.w + p2*v2.w + p3*v3.w;
    }
    for (; e < end; e++) {
        int s = __ldg(g_src_sorted + e);
        float4 kv = __ldg(&K4[(size_t)s * 32 + lane]);
        float p = kv.x*q.x + kv.y*q.y + kv.z*q.z + kv.w*q.w;
        p += __shfl_xor_sync(0xffffffffu, p, 1);
        p += __shfl_xor_sync(0xffffffffu, p, 2);
        p *= 0.25f;
        float4 v = __ldg(&V4[(size_t)s * 32 + lane]);
        acc.x += p*v.x; acc.y += p*v.y; acc.z += p*v.z; acc.w += p*v.w;
    }

    *(float4*)&out[(size_t)d * HD + lane * 4] = acc;
}

// ---------------------------------------------------------------------------
// Launch
// ---------------------------------------------------------------------------
extern "C" void kernel_launch(void* const* d_in, const int* in_sizes, int n_in,
                              void* d_out, int out_size)
{
    const float* h   = (const float*)d_in[0];
    const int*   src = (const int*)  d_in[1];
    const int*   dst = (const int*)  d_in[2];
    const float* Wq  = (const float*)d_in[3];
    const float* bq  = (const float*)d_in[4];
    const float* Wk  = (const float*)d_in[5];
    const float* bk  = (const float*)d_in[6];
    const float* Wv  = (const float*)d_in[7];
    const float* bv  = (const float*)d_in[8];
    float* out = (float*)d_out;

    int n_nodes = in_sizes[0] / IND;   // 50000
    int n_edges = in_sizes[1];         // 800000

    cudaFuncSetAttribute(qkv_gemm,
                         cudaFuncAttributeMaxDynamicSharedMemorySize,
                         GEMM_SMEM_BYTES);

    // Zero the degree histogram (device-symbol memset; capture-safe).
    void* deg_ptr = nullptr;
    cudaGetSymbolAddress(&deg_ptr, g_deg);
    cudaMemsetAsync(deg_ptr, 0, (size_t)n_nodes * sizeof(int));

    // CSR-by-dst build.
    int eb = (n_edges + 255) / 256;
    hist_kernel<<<eb, 256>>>(dst, n_edges);
    int nb = (n_nodes + 1023) / 1024;              // 49 for N=50000
    scan1_kernel<<<nb, 1024>>>(n_nodes);
    scan2_kernel<<<1, 64>>>(nb);
    int nb1 = (n_nodes + 1 + 1023) / 1024;
    scan3_kernel<<<nb1, 1024>>>(n_nodes, n_edges);
    scatter_kernel<<<eb, 256>>>(src, dst, n_edges);

    // QKV projections (independent of CSR build; same stream serializes).
    dim3 ggrid((n_nodes + 127) / 128, 3);
    qkv_gemm<<<ggrid, 256, GEMM_SMEM_BYTES>>>(h, Wq, bq, Wk, bk, Wv, bv, n_nodes);

    // Atomic-free aggregation: one warp per destination node.
    int nwarps = n_nodes;
    int ablocks = (nwarps * 32 + 255) / 256;
    aggregate_kernel<<<ablocks, 256>>>(out, n_nodes);
}